// round 10
// baseline (speedup 1.0000x reference)
#include <cuda_runtime.h>
#include <math.h>

// Problem constants (B=4, T=2048, D=1024, E=8, K=2)
#define BT           8192
#define DD           1024
#define DP           (DD + 4)              // padded row (16B-aligned, bank-shifted)
#define EE           8
#define TPB          256
#define ROWS_PER_CTA 8                     // one row per warp
#define NCTA         (BT / ROWS_PER_CTA)   // 1024

__device__ float        g_aux_part[NCTA];
__device__ unsigned int g_ctr;             // zero-init; self-resets each launch

__global__ __launch_bounds__(TPB, 5) void rlgate_main_kernel(
    const float* __restrict__ x,          // [BT, D]
    const float* __restrict__ eo,         // [E, BT, D]
    const float* __restrict__ rewards,    // [BT]
    const float* __restrict__ W,          // [D, E]
    const float* __restrict__ bias,       // [E]
    const float* __restrict__ baseline,   // scalar
    const float* __restrict__ noise,      // [BT, E]
    float* __restrict__ out,              // [BT*D (+aux slot)]
    int out_size)
{
    __shared__ float Wt[EE][DP];          // transposed gate weights (~33KB)
    __shared__ float s_aux[ROWS_PER_CTA];

    const int tid  = threadIdx.x;
    const int lane = tid & 31;
    const int warp = tid >> 5;

    const int row = blockIdx.x * ROWS_PER_CTA + warp;
    const float4* xr = (const float4*)(x + (size_t)row * DD);

    // Depth-4 prefetch issued BEFORE the smem barrier (overlaps W fill).
    float4 pf[4];
#pragma unroll
    for (int k = 0; k < 4; k++) pf[k] = __ldg(xr + lane + 32 * k);

    // ---- Load W [D,E] -> smem transposed Wt[E][D] (vectorized, padded) ----
    {
        const float4* W4 = (const float4*)W;
#pragma unroll
        for (int k = 0; k < (DD * EE / 4) / TPB; k++) {
            int i = tid + k * TPB;
            float4 v = __ldg(W4 + i);
            int d  = i >> 1;
            int e0 = (i & 1) * 4;
            Wt[e0 + 0][d] = v.x;
            Wt[e0 + 1][d] = v.y;
            Wt[e0 + 2][d] = v.z;
            Wt[e0 + 3][d] = v.w;
        }
    }
    __syncthreads();

    // ---- Phase 1: logits (depth-4 pipelined), one row per warp ----
    float acc[EE];
#pragma unroll
    for (int e = 0; e < EE; e++) acc[e] = 0.0f;

#pragma unroll
    for (int i = 0; i < 8; i++) {
        float4 a4 = pf[i & 3];
        if (i < 4) pf[i & 3] = __ldg(xr + lane + 32 * (i + 4));
        int j = lane + 32 * i;
#pragma unroll
        for (int e = 0; e < EE; e++) {
            // Wt row base is 16B-aligned (DP*4 = 4112 = 16*257)
            const float4 w = *(const float4*)&Wt[e][4 * j];
            acc[e] = fmaf(a4.x, w.x, fmaf(a4.y, w.y, fmaf(a4.z, w.z, fmaf(a4.w, w.w, acc[e]))));
        }
    }

    // ---- Hierarchical reduce: 8 values over 32 lanes in 23 SHFLs.
    // Ends with lane L holding the full-sum logit for e = L & 7.
    float le;
    {
#pragma unroll
        for (int j = 0; j < EE; j++) {
            acc[j] += __shfl_xor_sync(0xffffffffu, acc[j], 16);
            acc[j] += __shfl_xor_sync(0xffffffffu, acc[j], 8);
        }
        const bool b2 = (lane & 4) != 0;
        float t[4];
#pragma unroll
        for (int k = 0; k < 4; k++) {
            float send = b2 ? acc[k] : acc[k + 4];
            float recv = __shfl_xor_sync(0xffffffffu, send, 4);
            t[k] = (b2 ? acc[k + 4] : acc[k]) + recv;
        }
        const bool b1 = (lane & 2) != 0;
        float u2[2];
#pragma unroll
        for (int k = 0; k < 2; k++) {
            float send = b1 ? t[k] : t[k + 2];
            float recv = __shfl_xor_sync(0xffffffffu, send, 2);
            u2[k] = (b1 ? t[k + 2] : t[k]) + recv;
        }
        const bool b0 = (lane & 1) != 0;
        float send = b0 ? u2[0] : u2[1];
        float recv = __shfl_xor_sync(0xffffffffu, send, 1);
        le = (b0 ? u2[1] : u2[0]) + recv;
    }

    // ---- Phase 2: lane-parallel softmax + gumbel top-2 (all lanes, e=lane&7;
    //      the 4 groups of 8 compute identical results -> no broadcast needed) ----
    const int e = lane & 7;
    int i0, i1;
    float lp0, lp1;
    {
        le += __ldg(bias + e);

        float m = le;
#pragma unroll
        for (int off = 4; off; off >>= 1)
            m = fmaxf(m, __shfl_xor_sync(0xffffffffu, m, off));
        float p = __expf(le - m);
        float s = p;
#pragma unroll
        for (int off = 4; off; off >>= 1)
            s += __shfl_xor_sync(0xffffffffu, s, off);
        float lp = __logf(p / s + 1e-9f);     // absolute-error safe

        float u = __ldg(noise + (size_t)row * EE + e) * (1.0f - 2e-7f) + 1e-7f;
        // inner log needs full precision near u ~= 1; outer is abs-error safe
        float y = lp - __logf(-logf(u));

        float by = y; int bi = e;
#pragma unroll
        for (int off = 4; off; off >>= 1) {
            float oy = __shfl_xor_sync(0xffffffffu, by, off);
            int   oi = __shfl_xor_sync(0xffffffffu, bi, off);
            if (oy > by || (oy == by && oi < bi)) { by = oy; bi = oi; }
        }
        i0 = bi;
        float y2 = (e == i0) ? -1e30f : y;
        float by2 = y2; int bi2 = e;
#pragma unroll
        for (int off = 4; off; off >>= 1) {
            float oy = __shfl_xor_sync(0xffffffffu, by2, off);
            int   oi = __shfl_xor_sync(0xffffffffu, bi2, off);
            if (oy > by2 || (oy == by2 && oi < bi2)) { by2 = oy; bi2 = oi; }
        }
        i1 = bi2;

        lp0 = __shfl_sync(0xffffffffu, lp, (lane & 24) | i0);
        lp1 = __shfl_sync(0xffffffffu, lp, (lane & 24) | i1);

        if (lane == 0) {
            float adv = __ldg(rewards + row) - __ldg(baseline);
            s_aux[warp] = adv * (lp0 + lp1);
        }
    }

    // ---- Phase 3: combine gather (top-2 average), no barrier before it ----
    {
        const float4* qa = (const float4*)(eo + ((size_t)i0 * BT + row) * DD);
        const float4* qb = (const float4*)(eo + ((size_t)i1 * BT + row) * DD);
        float4* o = (float4*)(out + (size_t)row * DD);
#pragma unroll
        for (int i = 0; i < 8; i++) {
            int j = lane + 32 * i;
            float4 va = __ldcs(qa + j);
            float4 vb = __ldcs(qb + j);
            float4 rv;
            rv.x = (va.x + vb.x) * 0.5f;
            rv.y = (va.y + vb.y) * 0.5f;
            rv.z = (va.z + vb.z) * 0.5f;
            rv.w = (va.w + vb.w) * 0.5f;
            __stcs(o + j, rv);
        }
    }

    // ---- Aux finale at the very end (single barrier) ----
    __syncthreads();
    if (warp == 0) {
        int is_last = 0;
        if (lane == 0) {
            float s = 0.0f;
#pragma unroll
            for (int i = 0; i < ROWS_PER_CTA; i++) s += s_aux[i];
            g_aux_part[blockIdx.x] = s;
            __threadfence();
            unsigned p = atomicAdd(&g_ctr, 1u);
            is_last = (p == NCTA - 1);
        }
        is_last = __shfl_sync(0xffffffffu, is_last, 0);
        if (is_last) {
            double s = 0.0;
#pragma unroll
            for (int k = 0; k < NCTA / 32; k++)
                s += (double)__ldcg(&g_aux_part[lane + 32 * k]);
#pragma unroll
            for (int off = 16; off > 0; off >>= 1)
                s += __shfl_xor_sync(0xffffffffu, s, off);
            if (lane == 0) {
                out[out_size - 1] = -(float)(s / (double)BT);
                g_ctr = 0;                    // reset for next graph replay
            }
        }
    }
}

extern "C" void kernel_launch(void* const* d_in, const int* in_sizes, int n_in,
                              void* d_out, int out_size) {
    const float* x        = (const float*)d_in[0];
    const float* eo       = (const float*)d_in[1];
    const float* rewards  = (const float*)d_in[2];
    const float* W        = (const float*)d_in[3];
    const float* bias     = (const float*)d_in[4];
    const float* baseline = (const float*)d_in[5];
    const float* noise    = (const float*)d_in[6];
    // d_in[7] = top_k (K=2 hardcoded to match problem shapes)
    float* out = (float*)d_out;

    rlgate_main_kernel<<<NCTA, TPB>>>(x, eo, rewards, W, bias, baseline, noise,
                                      out, out_size);
}

// round 12
// speedup vs baseline: 1.2376x; 1.2376x over previous
#include <cuda_runtime.h>
#include <math.h>

// Problem constants (B=4, T=2048, D=1024, E=8, K=2)
#define BT           8192
#define DD           1024
#define EE           8
#define TPB          256
#define ROWS_PER_CTA 16
#define NCTA         (BT / ROWS_PER_CTA)   // 512

__device__ float        g_aux_part[NCTA];
__device__ unsigned int g_ctr;             // zero-init; self-resets each launch

__global__ __launch_bounds__(TPB, 4) void rlgate_main_kernel(
    const float* __restrict__ x,          // [BT, D]
    const float* __restrict__ eo,         // [E, BT, D]
    const float* __restrict__ rewards,    // [BT]
    const float* __restrict__ W,          // [D, E]
    const float* __restrict__ bias,       // [E]
    const float* __restrict__ baseline,   // scalar
    const float* __restrict__ noise,      // [BT, E]
    float* __restrict__ out,              // [BT*D (+aux slot)]
    int out_size)
{
    __shared__ float Wt[EE][DD];          // transposed gate weights, 32KB
    __shared__ float s_aux[ROWS_PER_CTA];

    const int tid  = threadIdx.x;
    const int lane = tid & 31;
    const int warp = tid >> 5;

    const int r0 = blockIdx.x * ROWS_PER_CTA + warp * 2;
    const int r1 = r0 + 1;

    const float4* x0 = (const float4*)(x + (size_t)r0 * DD);
    const float4* x1 = (const float4*)(x + (size_t)r1 * DD);

    // Depth-4 prefetch: iterations 0..3 issued BEFORE the smem barrier.
    float4 pa[4], pb[4];
#pragma unroll
    for (int k = 0; k < 4; k++) {
        pa[k] = __ldg(x0 + lane + 32 * k);
        pb[k] = __ldg(x1 + lane + 32 * k);
    }

    // ---- Load W [D,E] -> smem transposed Wt[E][D] (vectorized) ----
    {
        const float4* W4 = (const float4*)W;
#pragma unroll
        for (int k = 0; k < (DD * EE / 4) / TPB; k++) {
            int i = tid + k * TPB;
            float4 v = __ldg(W4 + i);
            int d  = i >> 1;
            int e0 = (i & 1) * 4;
            Wt[e0 + 0][d] = v.x;
            Wt[e0 + 1][d] = v.y;
            Wt[e0 + 2][d] = v.z;
            Wt[e0 + 3][d] = v.w;
        }
    }
    __syncthreads();

    // ---- Phase 1: logits for both rows (depth-4 pipelined) ----
    float acc0[EE], acc1[EE];
#pragma unroll
    for (int e = 0; e < EE; e++) { acc0[e] = 0.0f; acc1[e] = 0.0f; }

    const float4* Wt4 = (const float4*)Wt;   // Wt4[e*256 + j]

#pragma unroll
    for (int i = 0; i < 8; i++) {
        float4 a4 = pa[i & 3];
        float4 b4 = pb[i & 3];
        if (i < 4) {                          // refill slot with iter i+4
            int jn = lane + 32 * (i + 4);
            pa[i & 3] = __ldg(x0 + jn);
            pb[i & 3] = __ldg(x1 + jn);
        }
        int j = lane + 32 * i;
#pragma unroll
        for (int e = 0; e < EE; e++) {
            float4 w = Wt4[e * (DD / 4) + j];
            acc0[e] = fmaf(a4.x, w.x, fmaf(a4.y, w.y, fmaf(a4.z, w.z, fmaf(a4.w, w.w, acc0[e]))));
            acc1[e] = fmaf(b4.x, w.x, fmaf(b4.y, w.y, fmaf(b4.z, w.z, fmaf(b4.w, w.w, acc1[e]))));
        }
    }

    // ---- Hierarchical reduce: 16 values over 32 lanes in 31 SHFLs.
    // Ends with lane L holding the logit for row = bit3(L), e = L & 7.
    float le;
    {
#pragma unroll
        for (int j = 0; j < EE; j++) {
            acc0[j] += __shfl_xor_sync(0xffffffffu, acc0[j], 16);
            acc1[j] += __shfl_xor_sync(0xffffffffu, acc1[j], 16);
        }
        const bool rsel = (lane & 8) != 0;
        float t[8];
#pragma unroll
        for (int j = 0; j < EE; j++) {
            float send = rsel ? acc0[j] : acc1[j];
            float recv = __shfl_xor_sync(0xffffffffu, send, 8);
            t[j] = (rsel ? acc1[j] : acc0[j]) + recv;
        }
        const bool hi = (lane & 4) != 0;
        float u4[4];
#pragma unroll
        for (int k = 0; k < 4; k++) {
            float send = hi ? t[k] : t[k + 4];
            float recv = __shfl_xor_sync(0xffffffffu, send, 4);
            u4[k] = (hi ? t[k + 4] : t[k]) + recv;
        }
        const bool b1 = (lane & 2) != 0;
        float w2[2];
#pragma unroll
        for (int k = 0; k < 2; k++) {
            float send = b1 ? u4[k] : u4[k + 2];
            float recv = __shfl_xor_sync(0xffffffffu, send, 2);
            w2[k] = (b1 ? u4[k + 2] : u4[k]) + recv;
        }
        const bool b0 = (lane & 1) != 0;
        {
            float send = b0 ? w2[0] : w2[1];
            float recv = __shfl_xor_sync(0xffffffffu, send, 1);
            le = (b0 ? w2[1] : w2[0]) + recv;
        }
    }

    // ---- Phase 2: lane-parallel softmax + gumbel top-2 ----
    // lane = row*8 + e for lanes 0..15; lanes 16..31 duplicate.
    const int e    = lane & 7;
    const int half = (lane >> 3) & 1;
    const int row  = half ? r1 : r0;
    int i0, i1;
    {
        le += __ldg(bias + e);

        float m = le;
#pragma unroll
        for (int off = 4; off; off >>= 1)
            m = fmaxf(m, __shfl_xor_sync(0xffffffffu, m, off));
        float p = __expf(le - m);
        float s = p;
#pragma unroll
        for (int off = 4; off; off >>= 1)
            s += __shfl_xor_sync(0xffffffffu, s, off);
        float lp = __logf(p / s + 1e-9f);     // absolute-error safe

        float u = __ldg(noise + (size_t)row * EE + e) * (1.0f - 2e-7f) + 1e-7f;
        // inner log needs full precision near u ~= 1; outer is abs-error safe
        float y = lp - __logf(-logf(u));

        float by = y; int bi = e;
#pragma unroll
        for (int off = 4; off; off >>= 1) {
            float oy = __shfl_xor_sync(0xffffffffu, by, off);
            int   oi = __shfl_xor_sync(0xffffffffu, bi, off);
            if (oy > by || (oy == by && oi < bi)) { by = oy; bi = oi; }
        }
        i0 = bi;
        float y2 = (e == i0) ? -1e30f : y;
        float by2 = y2; int bi2 = e;
#pragma unroll
        for (int off = 4; off; off >>= 1) {
            float oy = __shfl_xor_sync(0xffffffffu, by2, off);
            int   oi = __shfl_xor_sync(0xffffffffu, bi2, off);
            if (oy > by2 || (oy == by2 && oi < bi2)) { by2 = oy; bi2 = oi; }
        }
        i1 = bi2;

        float lp0 = __shfl_sync(0xffffffffu, lp, (lane & 24) | i0);
        float lp1 = __shfl_sync(0xffffffffu, lp, (lane & 24) | i1);

        if (lane < 16 && (lane & 7) == 0) {   // lanes 0 and 8
            float adv = __ldg(rewards + row) - __ldg(baseline);
            s_aux[warp * 2 + half] = adv * (lp0 + lp1);
        }
    }
    // Broadcast expert pairs: lane0 -> r0, lane8 -> r1.
    const int a0 = __shfl_sync(0xffffffffu, i0, 0);
    const int a1 = __shfl_sync(0xffffffffu, i1, 0);
    const int b0 = __shfl_sync(0xffffffffu, i0, 8);
    const int b1 = __shfl_sync(0xffffffffu, i1, 8);

    // ---- Phase 3: combine gather, 2 j-positions per step -> 8 LDG.128
    //      in flight before any store (MLP 8 per warp) ----
    {
        const float4* qa = (const float4*)(eo + ((size_t)a0 * BT + r0) * DD);
        const float4* qb = (const float4*)(eo + ((size_t)a1 * BT + r0) * DD);
        const float4* qc = (const float4*)(eo + ((size_t)b0 * BT + r1) * DD);
        const float4* qd = (const float4*)(eo + ((size_t)b1 * BT + r1) * DD);
        float4* o0 = (float4*)(out + (size_t)r0 * DD);
        float4* o1 = (float4*)(out + (size_t)r1 * DD);
#pragma unroll
        for (int i = 0; i < 8; i += 2) {
            const int j0 = lane + 32 * i;
            const int j1 = lane + 32 * (i + 1);
            float4 va0 = __ldcs(qa + j0);
            float4 vb0 = __ldcs(qb + j0);
            float4 vc0 = __ldcs(qc + j0);
            float4 vd0 = __ldcs(qd + j0);
            float4 va1 = __ldcs(qa + j1);
            float4 vb1 = __ldcs(qb + j1);
            float4 vc1 = __ldcs(qc + j1);
            float4 vd1 = __ldcs(qd + j1);

            float4 r00, r10, r01, r11;
            r00.x = (va0.x + vb0.x) * 0.5f;  r00.y = (va0.y + vb0.y) * 0.5f;
            r00.z = (va0.z + vb0.z) * 0.5f;  r00.w = (va0.w + vb0.w) * 0.5f;
            r10.x = (vc0.x + vd0.x) * 0.5f;  r10.y = (vc0.y + vd0.y) * 0.5f;
            r10.z = (vc0.z + vd0.z) * 0.5f;  r10.w = (vc0.w + vd0.w) * 0.5f;
            r01.x = (va1.x + vb1.x) * 0.5f;  r01.y = (va1.y + vb1.y) * 0.5f;
            r01.z = (va1.z + vb1.z) * 0.5f;  r01.w = (va1.w + vb1.w) * 0.5f;
            r11.x = (vc1.x + vd1.x) * 0.5f;  r11.y = (vc1.y + vd1.y) * 0.5f;
            r11.z = (vc1.z + vd1.z) * 0.5f;  r11.w = (vc1.w + vd1.w) * 0.5f;

            __stcs(o0 + j0, r00);
            __stcs(o1 + j0, r10);
            __stcs(o0 + j1, r01);
            __stcs(o1 + j1, r11);
        }
    }

    // ---- Aux finale at the very end (single barrier) ----
    __syncthreads();
    if (warp == 0) {
        int is_last = 0;
        if (lane == 0) {
            float s = 0.0f;
#pragma unroll
            for (int i = 0; i < ROWS_PER_CTA; i++) s += s_aux[i];
            g_aux_part[blockIdx.x] = s;
            __threadfence();
            unsigned p = atomicAdd(&g_ctr, 1u);
            is_last = (p == NCTA - 1);
        }
        is_last = __shfl_sync(0xffffffffu, is_last, 0);
        if (is_last) {
            double s = 0.0;
#pragma unroll
            for (int k = 0; k < NCTA / 32; k++)
                s += (double)__ldcg(&g_aux_part[lane + 32 * k]);
#pragma unroll
            for (int off = 16; off > 0; off >>= 1)
                s += __shfl_xor_sync(0xffffffffu, s, off);
            if (lane == 0) {
                out[out_size - 1] = -(float)(s / (double)BT);
                g_ctr = 0;                    // reset for next graph replay
            }
        }
    }
}

extern "C" void kernel_launch(void* const* d_in, const int* in_sizes, int n_in,
                              void* d_out, int out_size) {
    const float* x        = (const float*)d_in[0];
    const float* eo       = (const float*)d_in[1];
    const float* rewards  = (const float*)d_in[2];
    const float* W        = (const float*)d_in[3];
    const float* bias     = (const float*)d_in[4];
    const float* baseline = (const float*)d_in[5];
    const float* noise    = (const float*)d_in[6];
    // d_in[7] = top_k (K=2 hardcoded to match problem shapes)
    float* out = (float*)d_out;

    rlgate_main_kernel<<<NCTA, TPB>>>(x, eo, rewards, W, bias, baseline, noise,
                                      out, out_size);
}

// round 14
// speedup vs baseline: 1.3223x; 1.0685x over previous
#include <cuda_runtime.h>
#include <math.h>

// Problem constants (B=4, T=2048, D=1024, E=8, K=2)
#define BT           8192
#define DD           1024
#define EE           8
#define TPB          128
#define ROWS_PER_CTA 16
#define NCTA         (BT / ROWS_PER_CTA)   // 512

__device__ float        g_aux_part[NCTA];
__device__ unsigned int g_ctr;             // zero-init; self-resets each launch

// Hierarchical reduce: 16 accs (2 rows x 8 experts) over 32 lanes, 31 SHFLs.
// Returns: lane L holds the logit for row = bit3(L), e = L & 7.
__device__ __forceinline__ float pair_reduce(float* acc0, float* acc1, int lane) {
#pragma unroll
    for (int j = 0; j < EE; j++) {
        acc0[j] += __shfl_xor_sync(0xffffffffu, acc0[j], 16);
        acc1[j] += __shfl_xor_sync(0xffffffffu, acc1[j], 16);
    }
    const bool rsel = (lane & 8) != 0;
    float t[8];
#pragma unroll
    for (int j = 0; j < EE; j++) {
        float send = rsel ? acc0[j] : acc1[j];
        float recv = __shfl_xor_sync(0xffffffffu, send, 8);
        t[j] = (rsel ? acc1[j] : acc0[j]) + recv;
    }
    const bool hi = (lane & 4) != 0;
    float u4[4];
#pragma unroll
    for (int k = 0; k < 4; k++) {
        float send = hi ? t[k] : t[k + 4];
        float recv = __shfl_xor_sync(0xffffffffu, send, 4);
        u4[k] = (hi ? t[k + 4] : t[k]) + recv;
    }
    const bool b1 = (lane & 2) != 0;
    float w2[2];
#pragma unroll
    for (int k = 0; k < 2; k++) {
        float send = b1 ? u4[k] : u4[k + 2];
        float recv = __shfl_xor_sync(0xffffffffu, send, 2);
        w2[k] = (b1 ? u4[k + 2] : u4[k]) + recv;
    }
    const bool b0 = (lane & 1) != 0;
    float send = b0 ? w2[0] : w2[1];
    float recv = __shfl_xor_sync(0xffffffffu, send, 1);
    return (b0 ? w2[1] : w2[0]) + recv;
}

// Lane-parallel softmax + gumbel top-2 for a row pair (lane = row*8+e layout).
// Outputs per-lane i0/i1 (valid group-wide) and aux term (valid on lanes 0/8).
__device__ __forceinline__ void softmax_top2(
    float le, int lane, int row,
    const float* __restrict__ bias, const float* __restrict__ noise,
    const float* __restrict__ rewards, const float* __restrict__ baseline,
    int& i0, int& i1, float& auxv)
{
    const int e = lane & 7;
    le += __ldg(bias + e);

    float m = le;
#pragma unroll
    for (int off = 4; off; off >>= 1)
        m = fmaxf(m, __shfl_xor_sync(0xffffffffu, m, off));
    float p = __expf(le - m);
    float s = p;
#pragma unroll
    for (int off = 4; off; off >>= 1)
        s += __shfl_xor_sync(0xffffffffu, s, off);
    float lp = __logf(p / s + 1e-9f);         // absolute-error safe

    float u = __ldg(noise + (size_t)row * EE + e) * (1.0f - 2e-7f) + 1e-7f;
    float y = lp - __logf(-logf(u));          // inner log kept precise

    float by = y; int bi = e;
#pragma unroll
    for (int off = 4; off; off >>= 1) {
        float oy = __shfl_xor_sync(0xffffffffu, by, off);
        int   oi = __shfl_xor_sync(0xffffffffu, bi, off);
        if (oy > by || (oy == by && oi < bi)) { by = oy; bi = oi; }
    }
    i0 = bi;
    float y2 = (e == i0) ? -1e30f : y;
    float by2 = y2; int bi2 = e;
#pragma unroll
    for (int off = 4; off; off >>= 1) {
        float oy = __shfl_xor_sync(0xffffffffu, by2, off);
        int   oi = __shfl_xor_sync(0xffffffffu, bi2, off);
        if (oy > by2 || (oy == by2 && oi < bi2)) { by2 = oy; bi2 = oi; }
    }
    i1 = bi2;

    float lp0 = __shfl_sync(0xffffffffu, lp, (lane & 24) | i0);
    float lp1 = __shfl_sync(0xffffffffu, lp, (lane & 24) | i1);
    float adv = __ldg(rewards + row) - __ldg(baseline);
    auxv = adv * (lp0 + lp1);
}

__global__ __launch_bounds__(TPB, 4) void rlgate_main_kernel(
    const float* __restrict__ x,          // [BT, D]
    const float* __restrict__ eo,         // [E, BT, D]
    const float* __restrict__ rewards,    // [BT]
    const float* __restrict__ W,          // [D, E]
    const float* __restrict__ bias,       // [E]
    const float* __restrict__ baseline,   // scalar
    const float* __restrict__ noise,      // [BT, E]
    float* __restrict__ out,              // [BT*D (+aux slot)]
    int out_size)
{
    __shared__ float Wt[EE][DD];          // transposed gate weights, 32KB
    __shared__ float s_aux[ROWS_PER_CTA];

    const int tid  = threadIdx.x;
    const int lane = tid & 31;
    const int warp = tid >> 5;            // 0..3

    // Each warp owns 4 rows: two pairs (q0,q1) and (q2,q3).
    const int q0 = blockIdx.x * ROWS_PER_CTA + warp * 4;
    const int q1 = q0 + 1, q2 = q0 + 2, q3 = q0 + 3;

    const float4* x0 = (const float4*)(x + (size_t)q0 * DD);
    const float4* x1 = (const float4*)(x + (size_t)q1 * DD);
    const float4* x2 = (const float4*)(x + (size_t)q2 * DD);
    const float4* x3 = (const float4*)(x + (size_t)q3 * DD);

    // Depth-4 prefetch for pair0 BEFORE the smem barrier.
    float4 pa[4], pb[4];
#pragma unroll
    for (int k = 0; k < 4; k++) {
        pa[k] = __ldg(x0 + lane + 32 * k);
        pb[k] = __ldg(x1 + lane + 32 * k);
    }

    // ---- Load W [D,E] -> smem transposed Wt[E][D] ----
    {
        const float4* W4 = (const float4*)W;
#pragma unroll
        for (int k = 0; k < (DD * EE / 4) / TPB; k++) {
            int i = tid + k * TPB;
            float4 v = __ldg(W4 + i);
            int d  = i >> 1;
            int e0 = (i & 1) * 4;
            Wt[e0 + 0][d] = v.x;
            Wt[e0 + 1][d] = v.y;
            Wt[e0 + 2][d] = v.z;
            Wt[e0 + 3][d] = v.w;
        }
    }
    __syncthreads();

    const float4* Wt4 = (const float4*)Wt;   // Wt4[e*256 + j]

    // ---- Gate pair0 (q0,q1), depth-4 pipelined ----
    float accA[EE], accB[EE];
#pragma unroll
    for (int e = 0; e < EE; e++) { accA[e] = 0.0f; accB[e] = 0.0f; }

#pragma unroll
    for (int i = 0; i < 8; i++) {
        float4 a4 = pa[i & 3];
        float4 b4 = pb[i & 3];
        if (i < 4) {
            int jn = lane + 32 * (i + 4);
            pa[i & 3] = __ldg(x0 + jn);
            pb[i & 3] = __ldg(x1 + jn);
        }
        int j = lane + 32 * i;
#pragma unroll
        for (int e = 0; e < EE; e++) {
            float4 w = Wt4[e * (DD / 4) + j];
            accA[e] = fmaf(a4.x, w.x, fmaf(a4.y, w.y, fmaf(a4.z, w.z, fmaf(a4.w, w.w, accA[e]))));
            accB[e] = fmaf(b4.x, w.x, fmaf(b4.y, w.y, fmaf(b4.z, w.z, fmaf(b4.w, w.w, accB[e]))));
        }
    }

    // x prefetch for pair1 (depth-2) — covers the SHFL-heavy reduce below.
    float4 pc[2], pd[2];
#pragma unroll
    for (int k = 0; k < 2; k++) {
        pc[k] = __ldg(x2 + lane + 32 * k);
        pd[k] = __ldg(x3 + lane + 32 * k);
    }

    // ---- Reduce + softmax/top-2 for pair0 ----
    {
        float le = pair_reduce(accA, accB, lane);
        const int half = (lane >> 3) & 1;
        const int row  = half ? q1 : q0;
        int i0, i1; float auxv;
        softmax_top2(le, lane, row, bias, noise, rewards, baseline, i0, i1, auxv);
        if (lane < 16 && (lane & 7) == 0)
            s_aux[warp * 4 + half] = auxv;
        // broadcast pair0 expert indices (lane0 -> q0, lane8 -> q1)
        accA[0] = __int_as_float(__shfl_sync(0xffffffffu, i0, 0));
        accA[1] = __int_as_float(__shfl_sync(0xffffffffu, i1, 0));
        accA[2] = __int_as_float(__shfl_sync(0xffffffffu, i0, 8));
        accA[3] = __int_as_float(__shfl_sync(0xffffffffu, i1, 8));
    }
    const int a0 = __float_as_int(accA[0]);
    const int a1 = __float_as_int(accA[1]);
    const int b0 = __float_as_int(accA[2]);
    const int b1 = __float_as_int(accA[3]);

    const float4* qa = (const float4*)(eo + ((size_t)a0 * BT + q0) * DD);
    const float4* qb = (const float4*)(eo + ((size_t)a1 * BT + q0) * DD);
    const float4* qc = (const float4*)(eo + ((size_t)b0 * BT + q1) * DD);
    const float4* qd = (const float4*)(eo + ((size_t)b1 * BT + q1) * DD);
    float4* o0 = (float4*)(out + (size_t)q0 * DD);
    float4* o1 = (float4*)(out + (size_t)q1 * DD);

    // ---- FUSED loop: stream pair0 while gating pair1 ----
    float accC[EE], accD[EE];
#pragma unroll
    for (int e = 0; e < EE; e++) { accC[e] = 0.0f; accD[e] = 0.0f; }

    float4 bufA[2], bufB[2], bufC[2], bufD[2];
    bufA[0] = __ldcs(qa + lane);
    bufB[0] = __ldcs(qb + lane);
    bufC[0] = __ldcs(qc + lane);
    bufD[0] = __ldcs(qd + lane);

#pragma unroll
    for (int i = 0; i < 8; i++) {
        // issue next stream loads (one iter ahead)
        if (i < 7) {
            int jn = lane + 32 * (i + 1);
            bufA[(i + 1) & 1] = __ldcs(qa + jn);
            bufB[(i + 1) & 1] = __ldcs(qb + jn);
            bufC[(i + 1) & 1] = __ldcs(qc + jn);
            bufD[(i + 1) & 1] = __ldcs(qd + jn);
        }
        // gate-iter i for pair1 (compute fills the load-latency window)
        {
            float4 a4 = pc[i & 1];
            float4 b4 = pd[i & 1];
            if (i < 6) {
                int jn = lane + 32 * (i + 2);
                pc[i & 1] = __ldg(x2 + jn);
                pd[i & 1] = __ldg(x3 + jn);
            }
            int j = lane + 32 * i;
#pragma unroll
            for (int e = 0; e < EE; e++) {
                float4 w = Wt4[e * (DD / 4) + j];
                accC[e] = fmaf(a4.x, w.x, fmaf(a4.y, w.y, fmaf(a4.z, w.z, fmaf(a4.w, w.w, accC[e]))));
                accD[e] = fmaf(b4.x, w.x, fmaf(b4.y, w.y, fmaf(b4.z, w.z, fmaf(b4.w, w.w, accD[e]))));
            }
        }
        // consume current stream buffer -> store
        {
            int j = lane + 32 * i;
            float4 va = bufA[i & 1], vb = bufB[i & 1];
            float4 vc = bufC[i & 1], vd = bufD[i & 1];
            float4 r0v, r1v;
            r0v.x = (va.x + vb.x) * 0.5f;  r0v.y = (va.y + vb.y) * 0.5f;
            r0v.z = (va.z + vb.z) * 0.5f;  r0v.w = (va.w + vb.w) * 0.5f;
            r1v.x = (vc.x + vd.x) * 0.5f;  r1v.y = (vc.y + vd.y) * 0.5f;
            r1v.z = (vc.z + vd.z) * 0.5f;  r1v.w = (vc.w + vd.w) * 0.5f;
            __stcs(o0 + j, r0v);
            __stcs(o1 + j, r1v);
        }
    }

    // ---- Reduce + softmax/top-2 for pair1 ----
    int c0, c1, d0, d1;
    {
        float le = pair_reduce(accC, accD, lane);
        const int half = (lane >> 3) & 1;
        const int row  = half ? q3 : q2;
        int i0, i1; float auxv;
        softmax_top2(le, lane, row, bias, noise, rewards, baseline, i0, i1, auxv);
        if (lane < 16 && (lane & 7) == 0)
            s_aux[warp * 4 + 2 + half] = auxv;
        c0 = __shfl_sync(0xffffffffu, i0, 0);
        c1 = __shfl_sync(0xffffffffu, i1, 0);
        d0 = __shfl_sync(0xffffffffu, i0, 8);
        d1 = __shfl_sync(0xffffffffu, i1, 8);
    }

    // ---- Stream pair1 (plain, like R8 phase 3) ----
    {
        const float4* ra = (const float4*)(eo + ((size_t)c0 * BT + q2) * DD);
        const float4* rb = (const float4*)(eo + ((size_t)c1 * BT + q2) * DD);
        const float4* rc = (const float4*)(eo + ((size_t)d0 * BT + q3) * DD);
        const float4* rd = (const float4*)(eo + ((size_t)d1 * BT + q3) * DD);
        float4* o2 = (float4*)(out + (size_t)q2 * DD);
        float4* o3 = (float4*)(out + (size_t)q3 * DD);
#pragma unroll
        for (int i = 0; i < 8; i++) {
            int j = lane + 32 * i;
            float4 va = __ldcs(ra + j);
            float4 vb = __ldcs(rb + j);
            float4 vc = __ldcs(rc + j);
            float4 vd = __ldcs(rd + j);
            float4 r0v, r1v;
            r0v.x = (va.x + vb.x) * 0.5f;  r0v.y = (va.y + vb.y) * 0.5f;
            r0v.z = (va.z + vb.z) * 0.5f;  r0v.w = (va.w + vb.w) * 0.5f;
            r1v.x = (vc.x + vd.x) * 0.5f;  r1v.y = (vc.y + vd.y) * 0.5f;
            r1v.z = (vc.z + vd.z) * 0.5f;  r1v.w = (vc.w + vd.w) * 0.5f;
            __stcs(o2 + j, r0v);
            __stcs(o3 + j, r1v);
        }
    }

    // ---- Aux finale (single barrier) ----
    __syncthreads();
    if (warp == 0) {
        int is_last = 0;
        if (lane == 0) {
            float s = 0.0f;
#pragma unroll
            for (int i = 0; i < ROWS_PER_CTA; i++) s += s_aux[i];
            g_aux_part[blockIdx.x] = s;
            __threadfence();
            unsigned p = atomicAdd(&g_ctr, 1u);
            is_last = (p == NCTA - 1);
        }
        is_last = __shfl_sync(0xffffffffu, is_last, 0);
        if (is_last) {
            double s = 0.0;
#pragma unroll
            for (int k = 0; k < NCTA / 32; k++)
                s += (double)__ldcg(&g_aux_part[lane + 32 * k]);
#pragma unroll
            for (int off = 16; off > 0; off >>= 1)
                s += __shfl_xor_sync(0xffffffffu, s, off);
            if (lane == 0) {
                out[out_size - 1] = -(float)(s / (double)BT);
                g_ctr = 0;                    // reset for next graph replay
            }
        }
    }
}

extern "C" void kernel_launch(void* const* d_in, const int* in_sizes, int n_in,
                              void* d_out, int out_size) {
    const float* x        = (const float*)d_in[0];
    const float* eo       = (const float*)d_in[1];
    const float* rewards  = (const float*)d_in[2];
    const float* W        = (const float*)d_in[3];
    const float* bias     = (const float*)d_in[4];
    const float* baseline = (const float*)d_in[5];
    const float* noise    = (const float*)d_in[6];
    // d_in[7] = top_k (K=2 hardcoded to match problem shapes)
    float* out = (float*)d_out;

    rlgate_main_kernel<<<NCTA, TPB>>>(x, eo, rewards, W, bias, baseline, noise,
                                      out, out_size);
}